// round 13
// baseline (speedup 1.0000x reference)
#include <cuda_runtime.h>
#include <cstdint>

// Neural CDE, B=128, T=1024, D=32, H=64, W=128.
// 32 clusters x 2 CTAs (64 CTAs, 512 thr). Each cluster owns 4 batches.
// vW2 (2112x128 fp32) ROW-SPLIT across the pair: each CTA streams only its
// 1056 rows (528KB) per step -> halves per-SM L1 traffic and chip L2 traffic
// vs R8. Every dot product stays inside one CTA (fp32-exact). Only yhat
// (128 floats/step) crosses CTAs: st.shared::cluster pushes into a parity
// double-buffered gather buffer, ordered by ONE barrier.cluster per step.
// Layer-3: 8 lanes/row, FFMA2 packed accumulation, 3-level shuffle
// reduction, double-buffered weight loads, fused tanh.approx.f32.

namespace {

constexpr int Tn = 1024;
constexpr int Dn = 32;
constexpr int Hn = 64;
constexpr int Wn = 128;
constexpr int Cn = Dn + 1;      // 33
constexpr int On = Hn * Cn;     // 2112
constexpr int CG = 2;           // CTAs per cluster
constexpr int NB = 4;           // batches per cluster (each CTA sees all 4)
constexpr int NCTA = 64;
constexpr int NT = 512;
constexpr int ROWSL = On / CG;  // 1056 rows of vW2 per CTA
constexpr int HL = Hn / CG;     // 32 h-values per CTA

using u64 = unsigned long long;

struct __align__(16) Smem {
  float w1[Wn * 132];     // vW1 full, rows padded to 132
  float w0s[Wn * 68];     // vW0 cols 1..64, rows padded to 68
  float w0t[Wn];          // vW0 col 0 (t coefficient)
  float b0[Wn];
  float b1[Wn];
  float b2s[ROWSL];       // vb2 slice
  float v[ROWSL * 4];     // [o_local*4 + b]
  float yh[2][NB * 68];   // gather: [slot][b*68 + h]
  float z1[NB * 132];
  float z2[NB * 132];
  float dx[NB * 36];
  float tcur;
  float pad_[3];
};

__device__ __forceinline__ uint32_t smem_u32(const void* p) {
  return (uint32_t)__cvta_generic_to_shared(const_cast<void*>(p));
}
__device__ __forceinline__ uint32_t mapa_rank(uint32_t laddr, uint32_t rank) {
  uint32_t r;
  asm("mapa.shared::cluster.u32 %0, %1, %2;" : "=r"(r) : "r"(laddr), "r"(rank));
  return r;
}
__device__ __forceinline__ void st_cluster(uint32_t addr, float v) {
  asm volatile("st.shared::cluster.f32 [%0], %1;" :: "r"(addr), "f"(v) : "memory");
}
__device__ __forceinline__ void cluster_sync() {
  asm volatile("barrier.cluster.arrive.aligned;" ::: "memory");
  asm volatile("barrier.cluster.wait.aligned;" ::: "memory");
}

__device__ __forceinline__ float lipswish(float x) {
  float e = __expf(-x);
  return __fdividef(0.909f * x, 1.0f + e);
}
__device__ __forceinline__ float tanha(float x) {
  float r;
  asm("tanh.approx.f32 %0, %1;" : "=f"(r) : "f"(x));
  return r;
}
__device__ __forceinline__ float dot4(float4 a, float4 b, float acc) {
  acc = fmaf(a.x, b.x, acc);
  acc = fmaf(a.y, b.y, acc);
  acc = fmaf(a.z, b.z, acc);
  acc = fmaf(a.w, b.w, acc);
  return acc;
}
__device__ __forceinline__ void ffma2(u64& acc, u64 a, u64 b) {
  asm("fma.rn.f32x2 %0, %1, %2, %0;" : "+l"(acc) : "l"(a), "l"(b));
}
__device__ __forceinline__ float hadd2(u64 a) {
  float lo, hi;
  asm("mov.b64 {%0, %1}, %2;" : "=f"(lo), "=f"(hi) : "l"(a));
  return lo + hi;
}

// One vf evaluation. Caller has pushed yhat into yh[slot] (local + remote
// halves) and set tcur. Starts with cluster_sync (orders peer pushes),
// ends with __syncthreads (v visible CTA-locally).
__device__ __forceinline__ void vf_eval(Smem& sm, int tid, int slot,
                                        const float* __restrict__ vW2,
                                        int rank) {
  cluster_sync();  // yh[slot] complete cluster-wide

  const int w = tid >> 2, b = tid & 3;

  // ---- layer 1: 512 tasks = 128 rows x 4 batches ----
  {
    float a = sm.b0[w] + sm.w0t[w] * sm.tcur;
    const float4* wr = reinterpret_cast<const float4*>(&sm.w0s[w * 68]);
    const float4* yr = reinterpret_cast<const float4*>(&sm.yh[slot][b * 68]);
#pragma unroll
    for (int q = 0; q < 16; ++q) a = dot4(wr[q], yr[q], a);
    sm.z1[b * 132 + w] = lipswish(a);
  }
  __syncthreads();

  // ---- layer 2 ----
  {
    float a = sm.b1[w];
    const float4* wr = reinterpret_cast<const float4*>(&sm.w1[w * 132]);
    const float4* zr = reinterpret_cast<const float4*>(&sm.z1[b * 132]);
#pragma unroll
    for (int q = 0; q < 32; ++q) a = dot4(wr[q], zr[q], a);
    sm.z2[b * 132 + w] = lipswish(a);
  }
  __syncthreads();

  // ---- layer 3: this CTA's 1056-row slice, streamed from L2 ----
  // 8 lanes per row (kl = lane&7 -> k-chunks kl*4 + j*32), sub = lane>>3
  // picks the row within a 4-row body. LDG.128 = 4 rows x 128B = 4 lines.
  {
    const int wid = tid >> 5;
    const int lane = tid & 31;
    const int sub = lane >> 3;
    const int kl = lane & 7;

    ulonglong2 zc[4][4];
#pragma unroll
    for (int bb = 0; bb < 4; ++bb)
#pragma unroll
      for (int j = 0; j < 4; ++j)
        zc[bb][j] = *reinterpret_cast<const ulonglong2*>(
            &sm.z2[bb * 132 + kl * 4 + j * 32]);

    // warps 0-7: 17 bodies (68 rows), warps 8-15: 16 bodies (64 rows)
    const int nbody = (wid < 8) ? 17 : 16;
    const int rbase = (wid < 8) ? wid * 68 : 544 + (wid - 8) * 64;
    const float* lane_base =
        vW2 + (size_t)(ROWSL * rank + rbase + sub) * Wn + kl * 4;

    ulonglong2 wA[4], wB[4];
    auto loadb = [&](ulonglong2* wv, int i) {
      const float* p = lane_base + (size_t)i * 512;  // 4 rows * 128 floats
#pragma unroll
      for (int j = 0; j < 4; ++j)
        wv[j] = *reinterpret_cast<const ulonglong2*>(p + j * 32);
    };
    auto body = [&](const ulonglong2* wv, int i) {
      u64 a0 = 0ull, a1 = 0ull, a2 = 0ull, a3 = 0ull;
#pragma unroll
      for (int j = 0; j < 4; ++j) {
        ffma2(a0, wv[j].x, zc[0][j].x); ffma2(a0, wv[j].y, zc[0][j].y);
        ffma2(a1, wv[j].x, zc[1][j].x); ffma2(a1, wv[j].y, zc[1][j].y);
        ffma2(a2, wv[j].x, zc[2][j].x); ffma2(a2, wv[j].y, zc[2][j].y);
        ffma2(a3, wv[j].x, zc[3][j].x); ffma2(a3, wv[j].y, zc[3][j].y);
      }
      float s0 = hadd2(a0), s1 = hadd2(a1), s2 = hadd2(a2), s3 = hadd2(a3);
#pragma unroll
      for (int m = 1; m < 8; m <<= 1) {
        s0 += __shfl_xor_sync(0xffffffffu, s0, m);
        s1 += __shfl_xor_sync(0xffffffffu, s1, m);
        s2 += __shfl_xor_sync(0xffffffffu, s2, m);
        s3 += __shfl_xor_sync(0xffffffffu, s3, m);
      }
      const int row = rbase + 4 * i + sub;
      if (kl == 0) {
        const float bias = sm.b2s[row];
        float4 vv;
        vv.x = tanha(s0 + bias);
        vv.y = tanha(s1 + bias);
        vv.z = tanha(s2 + bias);
        vv.w = tanha(s3 + bias);
        *reinterpret_cast<float4*>(&sm.v[row * 4]) = vv;
      }
    };

    loadb(wA, 0);
    int i = 0;
#pragma unroll 1
    for (; i + 2 <= nbody; i += 2) {
      loadb(wB, i + 1);
      body(wA, i);
      if (i + 2 < nbody) loadb(wA, i + 2);
      body(wB, i + 1);
    }
    if (i < nbody) body(wA, i);  // odd tail (17-body warps)
  }
  __syncthreads();
}

__global__ void __launch_bounds__(NT, 1) __cluster_dims__(CG, 1, 1)
ncde_kernel(const float* __restrict__ ts, const float* __restrict__ ys,
            const float* __restrict__ iW0, const float* __restrict__ ib0,
            const float* __restrict__ iW1, const float* __restrict__ ib1,
            const float* __restrict__ iW2, const float* __restrict__ ib2,
            const float* __restrict__ vW0, const float* __restrict__ vb0,
            const float* __restrict__ vW1, const float* __restrict__ vb1,
            const float* __restrict__ vW2, const float* __restrict__ vb2,
            const float* __restrict__ rW, const float* __restrict__ rb,
            float* __restrict__ out) {
  extern __shared__ char smem_raw[];
  Smem& sm = *reinterpret_cast<Smem*>(smem_raw);
  const int tid = threadIdx.x;
  const int rank = (int)(blockIdx.x & 1);
  const int cluster_b0 = (int)(blockIdx.x >> 1) * NB;

  // ---- resident small weights ----
  for (int i = tid; i < Wn * Wn; i += NT)
    sm.w1[(i >> 7) * 132 + (i & 127)] = vW1[i];
  for (int i = tid; i < Wn * 64; i += NT) {
    const int r = i >> 6, j = i & 63;
    sm.w0s[r * 68 + j] = vW0[r * 65 + 1 + j];
  }
  if (tid < Wn) {
    sm.w0t[tid] = vW0[tid * 65];
    sm.b0[tid] = vb0[tid];
    sm.b1[tid] = vb1[tid];
  }
  for (int i = tid; i < ROWSL; i += NT) sm.b2s[i] = vb2[ROWSL * rank + i];

  // ---- remote push addresses for yhat (tid < 128) ----
  const int h_l = tid >> 2;   // local h (0..31) for state threads
  const int bq = tid & 3;     // batch
  uint32_t rem0 = 0, rem1 = 0;
  if (tid < 128) {
    const uint32_t a0 = smem_u32(&sm.yh[0][bq * 68 + HL * rank + h_l]);
    const uint32_t a1 = smem_u32(&sm.yh[1][bq * 68 + HL * rank + h_l]);
    rem0 = mapa_rank(a0, (uint32_t)(rank ^ 1));
    rem1 = mapa_rank(a1, (uint32_t)(rank ^ 1));
  }

  // ---- x prefetch (tid < 132: b_p = tid/33, c_p = tid%33) ----
  const int b_p = tid / Cn;
  const int c_p = tid - b_p * Cn;
  const int gb_p = cluster_b0 + b_p;
  float xp = 0.f, xn = 0.f;
  if (tid < NB * Cn) {
    xp = (c_p == 0) ? ts[0] : ys[((size_t)gb_p * Tn) * Dn + (c_p - 1)];
    xn = (c_p == 0) ? ts[1] : ys[((size_t)gb_p * Tn + 1) * Dn + (c_p - 1)];
    sm.dx[b_p * 36 + c_p] = xp;  // stage x0 for the initial MLP
  }
  if (tid == 0) sm.tcur = ts[0];
  __syncthreads();

  // ---- initial MLP (redundant per CTA), z1/z2 as scratch ----
  {
    const int w = tid >> 2, b = tid & 3;
    float a = ib0[w];
    for (int j = 0; j < Cn; ++j) a = fmaf(iW0[w * Cn + j], sm.dx[b * 36 + j], a);
    sm.z1[b * 132 + w] = fmaxf(a, 0.f);
  }
  __syncthreads();
  {
    const int w = tid >> 2, b = tid & 3;
    float a = ib1[w];
    const float4* wr = reinterpret_cast<const float4*>(iW1 + (size_t)w * Wn);
    const float4* zr = reinterpret_cast<const float4*>(&sm.z1[b * 132]);
    for (int q = 0; q < 32; ++q) a = dot4(wr[q], zr[q], a);
    sm.z2[b * 132 + w] = fmaxf(a, 0.f);
  }
  __syncthreads();

  // per-thread recurrence state (tid < 128): h = HL*rank + h_l, batch bq
  float y_r = 0.f, yhat_r = 0.f, s_old_r = 0.f;
  if (tid < 128) {
    const int h = HL * rank + h_l;
    float a = ib2[h];
    const float4* wr = reinterpret_cast<const float4*>(iW2 + (size_t)h * Wn);
    const float4* zr = reinterpret_cast<const float4*>(&sm.z2[bq * 132]);
    for (int q = 0; q < 32; ++q) a = dot4(wr[q], zr[q], a);
    y_r = a;
    yhat_r = a;
    sm.yh[0][bq * 68 + HL * rank + h_l] = a;  // local half
    st_cluster(rem0, a);                      // remote half
  }

  vf_eval(sm, tid, 0, vW2, rank);  // v0 = vf(ts[0], y0)

  // ---- main scan over 1023 steps ----
#pragma unroll 1
  for (int t = 1; t < Tn; ++t) {
    __syncthreads();  // prior-step dx/v readers done before overwrite
    // phase 1: dx = x[t]-x[t-1]; prefetch x[t+1]; tcur = ts[t]
    if (tid < NB * Cn) {
      sm.dx[b_p * 36 + c_p] = xn - xp;
      xp = xn;
      if (tid == 0) sm.tcur = xp;  // (b=0,c=0) holds ts[t]
      const int tn = (t + 1 < Tn) ? (t + 1) : t;
      xn = (c_p == 0) ? ts[tn] : ys[((size_t)gb_p * Tn + tn) * Dn + (c_p - 1)];
    }
    __syncthreads();

    // phase 2: s_old = v.dx (local h rows); yhat update; stage + push
    const int slot = t & 1;
    if (tid < 128) {
      const float* vr = &sm.v[(h_l * Cn) * 4 + bq];
      const float* dxr = &sm.dx[bq * 36];
      float s = 0.f;
#pragma unroll
      for (int c = 0; c < Cn; ++c) s = fmaf(vr[c * 4], dxr[c], s);
      const float yh = 2.f * y_r - yhat_r + s;
      yhat_r = yh;
      s_old_r = s;
      sm.yh[slot][bq * 68 + HL * rank + h_l] = yh;
      st_cluster(slot ? rem1 : rem0, yh);
    }

    vf_eval(sm, tid, slot, vW2, rank);  // v <- vf(ts[t], yhat)

    // phase 4: y += 0.5 * (s_old + v_new.dx)
    if (tid < 128) {
      const float* vr = &sm.v[(h_l * Cn) * 4 + bq];
      const float* dxr = &sm.dx[bq * 36];
      float s = 0.f;
#pragma unroll
      for (int c = 0; c < Cn; ++c) s = fmaf(vr[c * 4], dxr[c], s);
      y_r += 0.5f * (s_old_r + s);
    }
  }

  // ---- readout: gather y halves into rank 0's yh[0], reduce there ----
  if (tid < 128) {
    if (rank == 0)
      sm.yh[0][bq * 68 + h_l] = y_r;
    else
      st_cluster(rem0, y_r);  // lands in rank0's h 32..63 region
  }
  cluster_sync();
  if (rank == 0 && tid < NB) {
    float a = rb[0];
    for (int h = 0; h < Hn; ++h) a = fmaf(sm.yh[0][tid * 68 + h], rW[h], a);
    out[cluster_b0 + tid] = a;
  }
}

}  // namespace

extern "C" void kernel_launch(void* const* d_in, const int* in_sizes, int n_in,
                              void* d_out, int out_size) {
  const float* ts  = (const float*)d_in[0];
  const float* ys  = (const float*)d_in[1];
  const float* iW0 = (const float*)d_in[2];
  const float* ib0 = (const float*)d_in[3];
  const float* iW1 = (const float*)d_in[4];
  const float* ib1 = (const float*)d_in[5];
  const float* iW2 = (const float*)d_in[6];
  const float* ib2 = (const float*)d_in[7];
  const float* vW0 = (const float*)d_in[8];
  const float* vb0 = (const float*)d_in[9];
  const float* vW1 = (const float*)d_in[10];
  const float* vb1 = (const float*)d_in[11];
  const float* vW2 = (const float*)d_in[12];
  const float* vb2 = (const float*)d_in[13];
  const float* rW  = (const float*)d_in[14];
  const float* rb  = (const float*)d_in[15];
  float* out = (float*)d_out;

  cudaFuncSetAttribute(ncde_kernel, cudaFuncAttributeMaxDynamicSharedMemorySize,
                       (int)sizeof(Smem));
  ncde_kernel<<<NCTA, NT, sizeof(Smem)>>>(ts, ys, iW0, ib0, iW1, ib1, iW2, ib2,
                                          vW0, vb0, vW1, vb1, vW2, vb2, rW, rb,
                                          out);
}